// round 7
// baseline (speedup 1.0000x reference)
#include <cuda_runtime.h>
#include <cuda_bf16.h>
#include <cstdint>

// MSDeformAttn on GB300 (sm_103a) — shfl-free, packed-f32x2 version
//   B=2, Hd=8, C=32, P=4, levels=4
//   SHAPES = [(100,150),(50,75),(25,38),(13,19)], L = Q = 19947
//
// One warp per (b,q,h). Lanes: 4 groups x 8 lanes.
//   group g = point index, sub s = channel quad -> each corner load is a
//   fully-used 128B line per group (ulonglong2 = 4 floats as 2 f32x2 pairs).
// Per-level (x,y,w) come from direct per-lane loads (uniform in each 8-lane
// group, L1-resident) instead of SHFL distribution: removes 12 SHFLs + the
// serializing 128B preamble load, so each level's gathers are independent.
// Accumulation uses Blackwell packed fma.rn.f32x2 (half the FFMA count).
// Out-of-bounds corners are zeroed through the bilinear weights (reference
// clip+mask semantics).

#define QTOT 19947
#define LTOT 19947
#define HD   8
#define CH   32
#define ROWV2 (HD * CH / 4)   // ulonglong2 stride between spatial positions = 64

__device__ __forceinline__ void ffma2(uint64_t& d, uint64_t a, uint64_t b) {
    asm("fma.rn.f32x2 %0, %1, %2, %0;" : "+l"(d) : "l"(a), "l"(b));
}
__device__ __forceinline__ void fadd2(uint64_t& d, uint64_t a) {
    asm("add.rn.f32x2 %0, %0, %1;" : "+l"(d) : "l"(a));
}
__device__ __forceinline__ uint64_t pack2(float w) {
    uint64_t r;
    asm("mov.b64 %0, {%1, %1};" : "=l"(r) : "f"(w));
    return r;
}

__global__ void __launch_bounds__(256, 8)
msda_kernel(const float* __restrict__ value,
            const float* __restrict__ loc,
            const float* __restrict__ attw,
            float* __restrict__ out)
{
    const int warp = threadIdx.x >> 5;
    const int lane = threadIdx.x & 31;
    const int q = blockIdx.x * 8 + warp;
    if (q >= QTOT) return;                 // uniform across warp

    const int bh = blockIdx.y;             // b*8 + h
    const int b  = bh >> 3;
    const int h  = bh & 7;

    const int group = lane >> 3;           // point index within each level
    const int sub   = lane & 7;            // channel quad

    const int qbh = (b * QTOT + q) * HD + h;

    // per-lane pointers to this group's (x,y) and weight for level l at [l*4]
    const float2* locp = (const float2*)loc + (size_t)qbh * 16 + group;
    const float*  awp  = attw + (size_t)qbh * 16 + group;

    const int Hs[4] = {100, 50, 25, 13};
    const int Ws[4] = {150, 75, 38, 19};
    const int Ss[4] = {0, 15000, 18750, 19700};

    // per-lane gather base: (b, h, channel-quad), 128-bit granules
    const ulonglong2* vbase = (const ulonglong2*)(value + ((size_t)b * LTOT) * (HD * CH)
                                                        + (size_t)h * CH) + sub;

    uint64_t acc0 = 0, acc1 = 0;   // f32x2 pairs: channels {4s,4s+1} and {4s+2,4s+3}
                                   // bit pattern 0 == (0.0f, 0.0f)

#pragma unroll
    for (int l = 0; l < 4; ++l) {
        const int Hh = Hs[l];
        const int Ww = Ws[l];

        const float2 xy = locp[l * 4];
        const float  wt = awp[l * 4];

        const float x = xy.x * (float)Ww - 0.5f;
        const float y = xy.y * (float)Hh - 0.5f;
        const float xf = floorf(x);
        const float yf = floorf(y);
        const float dx = x - xf;
        const float dy = y - yf;
        const int x0 = (int)xf;            // in [-1, Ww-1] for uniform locs
        const int y0 = (int)yf;            // in [-1, Hh-1]

        // validity folded into weights
        const float fx0 = ((unsigned)x0       < (unsigned)Ww) ? 1.f : 0.f;
        const float fx1 = ((unsigned)(x0 + 1) < (unsigned)Ww) ? 1.f : 0.f;
        const float fy0 = ((unsigned)y0       < (unsigned)Hh) ? 1.f : 0.f;
        const float fy1 = ((unsigned)(y0 + 1) < (unsigned)Hh) ? 1.f : 0.f;

        const float gy0 = wt * (1.f - dy) * fy0;
        const float gy1 = wt * dy * fy1;
        const float gx0 = (1.f - dx) * fx0;
        const float gx1 = dx * fx1;

        // clamped indices
        const int x0c = max(x0, 0);
        const int x1c = min(x0 + 1, Ww - 1);
        const int y0c = max(y0, 0);
        const int y1c = min(y0 + 1, Hh - 1);

        const ulonglong2* lb = vbase + Ss[l] * ROWV2;
        const int r00 = (y0c * Ww + x0c) * ROWV2;
        const int xs  = (x1c - x0c) * ROWV2;        // 0 or 64
        const int ys  = (y1c - y0c) * (Ww * ROWV2); // 0 or Ww*64

        // interleaved loads / packed FMAs (<=2 corner temporaries live)
        {
            const ulonglong2 va = lb[r00];
            const ulonglong2 vb = lb[r00 + xs];
            uint64_t w = pack2(gy0 * gx0);
            ffma2(acc0, va.x, w); ffma2(acc1, va.y, w);
            const ulonglong2 vc = lb[r00 + ys];
            w = pack2(gy0 * gx1);
            ffma2(acc0, vb.x, w); ffma2(acc1, vb.y, w);
            const ulonglong2 vd = lb[r00 + ys + xs];
            w = pack2(gy1 * gx0);
            ffma2(acc0, vc.x, w); ffma2(acc1, vc.y, w);
            w = pack2(gy1 * gx1);
            ffma2(acc0, vd.x, w); ffma2(acc1, vd.y, w);
        }
    }

    // ---- reduce the 4 point-groups (lanes s, s+8, s+16, s+24), packed adds ----
    {
        uint64_t t0 = __shfl_xor_sync(0xffffffffu, (unsigned long long)acc0, 8);
        uint64_t t1 = __shfl_xor_sync(0xffffffffu, (unsigned long long)acc1, 8);
        fadd2(acc0, t0); fadd2(acc1, t1);
        t0 = __shfl_xor_sync(0xffffffffu, (unsigned long long)acc0, 16);
        t1 = __shfl_xor_sync(0xffffffffu, (unsigned long long)acc1, 16);
        fadd2(acc0, t0); fadd2(acc1, t1);
    }

    if (group == 0) {
        // out[b, q, h*32 + 4*sub .. +4) : 8 lanes x 16B = one 128B store
        ulonglong2 r; r.x = acc0; r.y = acc1;
        *(ulonglong2*)(out + (size_t)qbh * CH + sub * 4) = r;
    }
}

extern "C" void kernel_launch(void* const* d_in, const int* in_sizes, int n_in,
                              void* d_out, int out_size)
{
    const float* value = (const float*)d_in[0];
    const float* loc   = (const float*)d_in[3];
    const float* attw  = (const float*)d_in[4];
    float* out = (float*)d_out;

    dim3 grid((QTOT + 7) / 8, 2 * HD, 1);
    msda_kernel<<<grid, 256>>>(value, loc, attw, out);
}